// round 5
// baseline (speedup 1.0000x reference)
#include <cuda_runtime.h>

#define LL 32768
#define NN 2048
#define DD 64
#define HH 256
#define KIN 205
#define MTILE 32        // tokens per CTA
#define ASTR 34         // As row stride (32 tokens + 2 pad)
#define KT 8            // K-panel depth

struct Sizes {
    int c, lat, outN;
    int w0, w1, w2, w3, w4;
    int b0, b1, b2, b3, b4;
};

// ---- one MLP layer: As[K][32] (k-major) -> As[256][32], in place -----------
// Ws: 8x256 panel staged from global each iteration. Plain loads, plain syncs.
__device__ __forceinline__ void gemm_layer(float* As, float (*Ws)[HH],
                                           const float* __restrict__ Wg, int wN,
                                           const float* __restrict__ bg, int bN,
                                           int nP, int Kvalid)
{
    const int t  = threadIdx.x;
    const int ty = t >> 5;          // warp id: token group (4 tokens)
    const int tx = t & 31;          // lane: col residue (cols tx + 32*j)

    float acc[4][8];
#pragma unroll
    for (int i = 0; i < 4; ++i)
#pragma unroll
        for (int j = 0; j < 8; ++j) acc[i][j] = 0.f;

    for (int p = 0; p < nP; ++p) {
        // stage panel p: KT x 256 floats, 2048 elems, 8 per thread, coalesced
#pragma unroll
        for (int q = 0; q < (KT * HH) / 256; ++q) {
            int idx = q * 256 + t;
            int kk  = idx >> 8;
            int c   = idx & 255;
            int gk  = p * KT + kk;
            float v = 0.f;
            if (gk < Kvalid) v = __ldg(Wg + min(gk * HH + c, wN - 1));
            Ws[kk][c] = v;
        }
        __syncthreads();            // panel visible

        const float* as = As + p * KT * ASTR + ty * 4;
#pragma unroll
        for (int kk = 0; kk < KT; ++kk) {
            float a0 = as[kk * ASTR + 0];   // broadcast within warp
            float a1 = as[kk * ASTR + 1];
            float a2 = as[kk * ASTR + 2];
            float a3 = as[kk * ASTR + 3];
#pragma unroll
            for (int j = 0; j < 8; ++j) {
                float wv = Ws[kk][tx + 32 * j];   // stride-1: conflict-free
                acc[0][j] += a0 * wv;
                acc[1][j] += a1 * wv;
                acc[2][j] += a2 * wv;
                acc[3][j] += a3 * wv;
            }
        }
        __syncthreads();            // panel reads done before next overwrite
    }

    // epilogue: bias + relu, write back in place (k-major for next layer)
#pragma unroll
    for (int j = 0; j < 8; ++j) {
        int col = tx + 32 * j;
        float b = __ldg(bg + min(col, bN - 1));
#pragma unroll
        for (int i = 0; i < 4; ++i) {
            float v = fmaxf(acc[i][j] + b, 0.f);
            As[col * ASTR + ty * 4 + i] = v;
        }
    }
    __syncthreads();
}

// ---- fused kernel -----------------------------------------------------------
__global__ void __launch_bounds__(256)
lisa_kernel(const float* __restrict__ coord,  const float* __restrict__ latent,
            const float* __restrict__ W0, const float* __restrict__ b0,
            const float* __restrict__ W1, const float* __restrict__ b1,
            const float* __restrict__ W2, const float* __restrict__ b2,
            const float* __restrict__ W3, const float* __restrict__ b3,
            const float* __restrict__ W4, const float* __restrict__ b4,
            float* __restrict__ out, Sizes sz)
{
    __shared__ float As[HH * ASTR];        // 256 x 34 = 34816 B
    __shared__ float Ws[KT][HH];           // 8 x 256  =  8192 B

    const int t = threadIdx.x;
    const int w = t >> 5, lane = t & 31;
    const int tok0 = blockIdx.x * MTILE;
    const int bb = tok0 / LL;

    // zero feature rows [KIN, 256) once (covers layer-0 K padding)
    for (int i = t; i < (HH - KIN) * ASTR; i += 256)
        As[KIN * ASTR + i] = 0.f;

    // ---- feature build: coord | PE(12) | sampled(192), k-major --------------
#pragma unroll 1
    for (int tt = 0; tt < 4; ++tt) {
        int tl = w * 4 + tt;               // local token (8 warps x 4)
        float c = __ldg(coord + min(tok0 + tl, sz.c - 1));
        float ix  = c * (float)NN - 0.5f;
        float x0f = floorf(ix);
        float fr  = ix - x0f;
        int x0 = (int)x0f;
        int i0 = min(max(x0, 0), NN - 1);
        int i1 = min(max(x0 + 1, 0), NN - 1);
        if (lane == 0) As[tl] = c;
        if (lane >= 1 && lane <= 12) {
            int k = lane - 1;
            float ang = c * (float)(1 << (k >> 1));
            As[(1 + k) * ASTR + tl] = (k & 1) ? cosf(ang) : sinf(ang);
        }
        float om = 1.f - fr;
#pragma unroll
        for (int r = 0; r < 6; ++r) {
            int ch = r * 32 + lane;        // 0..191, coalesced across lanes
            int s  = ch >> 6;              // 0:prev 1:self 2:next
            int d  = ch & 63;
            int j0 = min(max(i0 + s - 1, 0), NN - 1);
            int j1 = min(max(i1 + s - 1, 0), NN - 1);
            int g0 = min(bb * NN * DD + j0 * DD + d, sz.lat - 1);
            int g1 = min(bb * NN * DD + j1 * DD + d, sz.lat - 1);
            float v = om * __ldg(latent + g0) + fr * __ldg(latent + g1);
            As[(13 + ch) * ASTR + tl] = v;
        }
    }
    __syncthreads();

    gemm_layer(As, Ws, W0, sz.w0, b0, sz.b0, (KIN + KT - 1) / KT, KIN);
    gemm_layer(As, Ws, W1, sz.w1, b1, sz.b1, HH / KT, HH);
    gemm_layer(As, Ws, W2, sz.w2, b2, sz.b2, HH / KT, HH);
    gemm_layer(As, Ws, W3, sz.w3, b3, sz.b3, HH / KT, HH);

    // ---- final 256 -> 1 ------------------------------------------------------
    float* w4s = &Ws[0][0];                // 256 floats
    float* red = &Ws[0][0] + 256;          // 256 floats (8 parts x 32 tokens)
    w4s[t] = __ldg(W4 + min(t, sz.w4 - 1));
    __syncthreads();
    int tok = t & 31, part = t >> 5;       // 8 parts of 32 k each
    float s = 0.f;
#pragma unroll 8
    for (int k = part * 32; k < part * 32 + 32; ++k)
        s += As[k * ASTR + tok] * w4s[k];
    red[part * 32 + tok] = s;
    __syncthreads();
    if (t < MTILE && tok0 + t < sz.outN) {
        float r = __ldg(b4);
#pragma unroll
        for (int pp = 0; pp < 8; ++pp) r += red[pp * 32 + t];
        out[tok0 + t] = r;
    }
}

// ---- size-based input resolution (elements OR bytes; any ordering) ----------
extern "C" void kernel_launch(void* const* d_in, const int* in_sizes, int n_in,
                              void* d_out, int out_size) {
    long long es[64];
    int m = n_in > 64 ? 64 : n_in;
    bool bytemode = false;
    for (int i = 0; i < m; ++i) if (in_sizes[i] == 4194304) bytemode = true;
    for (int i = 0; i < m; ++i)
        es[i] = bytemode ? (long long)in_sizes[i] / 4 : (long long)in_sizes[i];
    long long outN = bytemode ? (long long)out_size / 4 : (long long)out_size;

    int iCoord = -1, iLat = -1, iW0 = -1, iB4 = -1;
    int idx65[3];  int n65 = 0;
    int idx256[5]; int n256 = 0;
    for (int i = 0; i < m; ++i) {
        long long s = es[i];
        if      (s == 262144)  iCoord = i;
        else if (s == 1048576) iLat   = i;
        else if (s == 52480)   iW0    = i;
        else if (s == 1)       iB4    = i;
        else if (s == 65536 && n65 < 3)  idx65[n65++]  = i;
        else if (s == 256   && n256 < 5) idx256[n256++] = i;
    }

    int iW1, iW2, iW3, iW4, iB0, iB1, iB2, iB3;
    if (n65 == 3 && n256 == 5 && iCoord >= 0 && iLat >= 0 && iW0 >= 0 && iB4 >= 0) {
        iW1 = idx65[0]; iW2 = idx65[1]; iW3 = idx65[2];
        if (idx256[0] < idx65[0]) {     // biases interleaved (declaration order)
            iB0 = idx256[0]; iB1 = idx256[1]; iB2 = idx256[2];
            iB3 = idx256[3]; iW4 = idx256[4];
        } else {                        // W-block first (sorted order)
            iW4 = idx256[0]; iB0 = idx256[1]; iB1 = idx256[2];
            iB2 = idx256[3]; iB3 = idx256[4];
        }
    } else {
        iCoord = 0 % m;  iLat = 1 % m;  iW0 = 2 % m;  iB0 = 3 % m;
        iW1 = 4 % m;     iB1 = 5 % m;   iW2 = 6 % m;  iB2 = 7 % m;
        iW3 = 8 % m;     iB3 = 9 % m;   iW4 = 10 % m; iB4 = 11 % m;
    }

    Sizes sz;
    sz.c  = (int)es[iCoord]; sz.lat = (int)es[iLat]; sz.outN = (int)outN;
    sz.w0 = (int)es[iW0]; sz.w1 = (int)es[iW1]; sz.w2 = (int)es[iW2];
    sz.w3 = (int)es[iW3]; sz.w4 = (int)es[iW4];
    sz.b0 = (int)es[iB0]; sz.b1 = (int)es[iB1]; sz.b2 = (int)es[iB2];
    sz.b3 = (int)es[iB3]; sz.b4 = (int)es[iB4];

    const float* coord  = (const float*)d_in[iCoord];
    const float* latent = (const float*)d_in[iLat];
    const float* W0 = (const float*)d_in[iW0]; const float* b0 = (const float*)d_in[iB0];
    const float* W1 = (const float*)d_in[iW1]; const float* b1 = (const float*)d_in[iB1];
    const float* W2 = (const float*)d_in[iW2]; const float* b2 = (const float*)d_in[iB2];
    const float* W3 = (const float*)d_in[iW3]; const float* b3 = (const float*)d_in[iB3];
    const float* W4 = (const float*)d_in[iW4]; const float* b4 = (const float*)d_in[iB4];

    int blocks = (int)((outN + MTILE - 1) / MTILE);   // 8192 expected
    lisa_kernel<<<blocks, 256>>>(coord, latent,
                                 W0, b0, W1, b1, W2, b2, W3, b3, W4, b4,
                                 (float*)d_out, sz);
}

// round 6
// speedup vs baseline: 1.4135x; 1.4135x over previous
#include <cuda_runtime.h>

typedef unsigned long long ull;

#define LL 32768
#define NN 2048
#define DD 64
#define HH 256
#define KIN 205
#define MTILE 32        // tokens per CTA
#define ASTR 34         // As row stride (32 tokens + 2 pad)
#define KT 8            // K-panel depth

struct Sizes {
    int c, lat, outN;
    int w0, w1, w2, w3, w4;
    int b0, b1, b2, b3, b4;
};

// ---- Blackwell packed-fp32 helpers ------------------------------------------
__device__ __forceinline__ ull pack2(float x) {
    ull r; unsigned u = __float_as_uint(x);
    asm("mov.b64 %0, {%1, %1};" : "=l"(r) : "r"(u));
    return r;
}
__device__ __forceinline__ void fma2(ull& acc, ull a, ull b) {
    asm("fma.rn.f32x2 %0, %1, %2, %0;" : "+l"(acc) : "l"(a), "l"(b));
}

// ---- one MLP layer: As[K][32] (k-major) -> As[256][32], in place ------------
// Lane tx owns col-pairs {2tx+64j, 2tx+64j+1}, j=0..3  (natural ull in Ws row).
__device__ __forceinline__ void gemm_layer(float* As, float (*Ws)[HH],
                                           const float* __restrict__ Wg, int wN,
                                           const float* __restrict__ bg, int bN,
                                           int nP, int Kvalid)
{
    const int t  = threadIdx.x;
    const int ty = t >> 5;          // warp id: token group (4 tokens)
    const int tx = t & 31;

    ull acc[4][4];                  // [token][col-pair], f32x2 packed
#pragma unroll
    for (int i = 0; i < 4; ++i)
#pragma unroll
        for (int j = 0; j < 4; ++j) acc[i][j] = 0ULL;

    for (int p = 0; p < nP; ++p) {
        // stage panel p: KT x 256 floats = 512 float4, 2 per thread, coalesced
#pragma unroll
        for (int q = 0; q < 2; ++q) {
            int idx = q * 256 + t;          // 0..511
            int kk  = idx >> 6;             // 64 float4 per row
            int c4  = idx & 63;
            int gk  = p * KT + kk;
            float4 v = make_float4(0.f, 0.f, 0.f, 0.f);
            if (gk < Kvalid && (gk * HH + c4 * 4 + 4) <= wN)
                v = __ldg(reinterpret_cast<const float4*>(Wg + (size_t)gk * HH + c4 * 4));
            *reinterpret_cast<float4*>(&Ws[kk][c4 * 4]) = v;
        }
        __syncthreads();            // panel visible

        const float* as = As + p * KT * ASTR + ty * 4;
#pragma unroll
        for (int kk = 0; kk < KT; ++kk) {
            const ull* wr = reinterpret_cast<const ull*>(&Ws[kk][0]);
            ull w0 = wr[tx];        // cols 2tx,2tx+1      (LDS.64, phase-split ok)
            ull w1 = wr[tx + 32];   // cols 2tx+64,+65
            ull w2 = wr[tx + 64];
            ull w3 = wr[tx + 96];
            ull a0 = pack2(as[kk * ASTR + 0]);   // broadcast token scalars
            ull a1 = pack2(as[kk * ASTR + 1]);
            ull a2 = pack2(as[kk * ASTR + 2]);
            ull a3 = pack2(as[kk * ASTR + 3]);
            fma2(acc[0][0], a0, w0); fma2(acc[0][1], a0, w1);
            fma2(acc[0][2], a0, w2); fma2(acc[0][3], a0, w3);
            fma2(acc[1][0], a1, w0); fma2(acc[1][1], a1, w1);
            fma2(acc[1][2], a1, w2); fma2(acc[1][3], a1, w3);
            fma2(acc[2][0], a2, w0); fma2(acc[2][1], a2, w1);
            fma2(acc[2][2], a2, w2); fma2(acc[2][3], a2, w3);
            fma2(acc[3][0], a3, w0); fma2(acc[3][1], a3, w1);
            fma2(acc[3][2], a3, w2); fma2(acc[3][3], a3, w3);
        }
        __syncthreads();            // panel reads done before next overwrite
    }

    // epilogue: bias + relu, write back in place (k-major for next layer)
#pragma unroll
    for (int j = 0; j < 4; ++j) {
        int c0 = 2 * (tx + 32 * j);         // even col of the pair
        float bia0 = __ldg(bg + min(c0,     bN - 1));
        float bia1 = __ldg(bg + min(c0 + 1, bN - 1));
#pragma unroll
        for (int i = 0; i < 4; ++i) {
            ull v = acc[i][j];
            float v0 = fmaxf(__uint_as_float((unsigned)v)         + bia0, 0.f);
            float v1 = fmaxf(__uint_as_float((unsigned)(v >> 32)) + bia1, 0.f);
            As[c0 * ASTR       + ty * 4 + i] = v0;
            As[(c0 + 1) * ASTR + ty * 4 + i] = v1;
        }
    }
    __syncthreads();
}

// ---- fused kernel -----------------------------------------------------------
__global__ void __launch_bounds__(256)
lisa_kernel(const float* __restrict__ coord,  const float* __restrict__ latent,
            const float* __restrict__ W0, const float* __restrict__ b0,
            const float* __restrict__ W1, const float* __restrict__ b1,
            const float* __restrict__ W2, const float* __restrict__ b2,
            const float* __restrict__ W3, const float* __restrict__ b3,
            const float* __restrict__ W4, const float* __restrict__ b4,
            float* __restrict__ out, Sizes sz)
{
    __shared__ float As[HH * ASTR];        // 256 x 34 x4 = 34816 B
    __shared__ float Ws[KT][HH];           // 8 x 256 x4  =  8192 B

    const int t = threadIdx.x;
    const int w = t >> 5, lane = t & 31;
    const int tok0 = blockIdx.x * MTILE;
    const int bb = tok0 / LL;

    // zero feature rows [KIN, 256) once (covers layer-0 K padding)
    for (int i = t; i < (HH - KIN) * ASTR; i += 256)
        As[KIN * ASTR + i] = 0.f;

    // ---- feature build: coord | PE(12) | sampled(192), k-major --------------
#pragma unroll 1
    for (int tt = 0; tt < 4; ++tt) {
        int tl = w * 4 + tt;               // local token (8 warps x 4)
        float c = __ldg(coord + min(tok0 + tl, sz.c - 1));
        float ix  = c * (float)NN - 0.5f;
        float x0f = floorf(ix);
        float fr  = ix - x0f;
        int x0 = (int)x0f;
        int i0 = min(max(x0, 0), NN - 1);
        int i1 = min(max(x0 + 1, 0), NN - 1);
        if (lane == 0) As[tl] = c;
        if (lane >= 1 && lane <= 12) {
            int k = lane - 1;
            float ang = c * (float)(1 << (k >> 1));
            As[(1 + k) * ASTR + tl] = (k & 1) ? cosf(ang) : sinf(ang);
        }
        float om = 1.f - fr;
#pragma unroll
        for (int r = 0; r < 6; ++r) {
            int ch = r * 32 + lane;        // 0..191, coalesced across lanes
            int s  = ch >> 6;              // 0:prev 1:self 2:next
            int d  = ch & 63;
            int j0 = min(max(i0 + s - 1, 0), NN - 1);
            int j1 = min(max(i1 + s - 1, 0), NN - 1);
            int g0 = min(bb * NN * DD + j0 * DD + d, sz.lat - 1);
            int g1 = min(bb * NN * DD + j1 * DD + d, sz.lat - 1);
            float v = om * __ldg(latent + g0) + fr * __ldg(latent + g1);
            As[(13 + ch) * ASTR + tl] = v;
        }
    }
    __syncthreads();

    gemm_layer(As, Ws, W0, sz.w0, b0, sz.b0, (KIN + KT - 1) / KT, KIN);
    gemm_layer(As, Ws, W1, sz.w1, b1, sz.b1, HH / KT, HH);
    gemm_layer(As, Ws, W2, sz.w2, b2, sz.b2, HH / KT, HH);
    gemm_layer(As, Ws, W3, sz.w3, b3, sz.b3, HH / KT, HH);

    // ---- final 256 -> 1 ------------------------------------------------------
    float* w4s = &Ws[0][0];                // 256 floats
    float* red = &Ws[0][0] + 256;          // 256 floats (8 parts x 32 tokens)
    w4s[t] = __ldg(W4 + min(t, sz.w4 - 1));
    __syncthreads();
    int tok = t & 31, part = t >> 5;       // 8 parts of 32 k each
    float s = 0.f;
#pragma unroll 8
    for (int k = part * 32; k < part * 32 + 32; ++k)
        s += As[k * ASTR + tok] * w4s[k];
    red[part * 32 + tok] = s;
    __syncthreads();
    if (t < MTILE && tok0 + t < sz.outN) {
        float r = __ldg(b4);
#pragma unroll
        for (int pp = 0; pp < 8; ++pp) r += red[pp * 32 + t];
        out[tok0 + t] = r;
    }
}

// ---- size-based input resolution (elements OR bytes; any ordering) ----------
extern "C" void kernel_launch(void* const* d_in, const int* in_sizes, int n_in,
                              void* d_out, int out_size) {
    long long es[64];
    int m = n_in > 64 ? 64 : n_in;
    bool bytemode = false;
    for (int i = 0; i < m; ++i) if (in_sizes[i] == 4194304) bytemode = true;
    for (int i = 0; i < m; ++i)
        es[i] = bytemode ? (long long)in_sizes[i] / 4 : (long long)in_sizes[i];
    long long outN = bytemode ? (long long)out_size / 4 : (long long)out_size;

    int iCoord = -1, iLat = -1, iW0 = -1, iB4 = -1;
    int idx65[3];  int n65 = 0;
    int idx256[5]; int n256 = 0;
    for (int i = 0; i < m; ++i) {
        long long s = es[i];
        if      (s == 262144)  iCoord = i;
        else if (s == 1048576) iLat   = i;
        else if (s == 52480)   iW0    = i;
        else if (s == 1)       iB4    = i;
        else if (s == 65536 && n65 < 3)  idx65[n65++]  = i;
        else if (s == 256   && n256 < 5) idx256[n256++] = i;
    }

    int iW1, iW2, iW3, iW4, iB0, iB1, iB2, iB3;
    if (n65 == 3 && n256 == 5 && iCoord >= 0 && iLat >= 0 && iW0 >= 0 && iB4 >= 0) {
        iW1 = idx65[0]; iW2 = idx65[1]; iW3 = idx65[2];
        if (idx256[0] < idx65[0]) {     // biases interleaved (declaration order)
            iB0 = idx256[0]; iB1 = idx256[1]; iB2 = idx256[2];
            iB3 = idx256[3]; iW4 = idx256[4];
        } else {                        // W-block first (sorted order)
            iW4 = idx256[0]; iB0 = idx256[1]; iB1 = idx256[2];
            iB2 = idx256[3]; iB3 = idx256[4];
        }
    } else {
        iCoord = 0 % m;  iLat = 1 % m;  iW0 = 2 % m;  iB0 = 3 % m;
        iW1 = 4 % m;     iB1 = 5 % m;   iW2 = 6 % m;  iB2 = 7 % m;
        iW3 = 8 % m;     iB3 = 9 % m;   iW4 = 10 % m; iB4 = 11 % m;
    }

    Sizes sz;
    sz.c  = (int)es[iCoord]; sz.lat = (int)es[iLat]; sz.outN = (int)outN;
    sz.w0 = (int)es[iW0]; sz.w1 = (int)es[iW1]; sz.w2 = (int)es[iW2];
    sz.w3 = (int)es[iW3]; sz.w4 = (int)es[iW4];
    sz.b0 = (int)es[iB0]; sz.b1 = (int)es[iB1]; sz.b2 = (int)es[iB2];
    sz.b3 = (int)es[iB3]; sz.b4 = (int)es[iB4];

    const float* coord  = (const float*)d_in[iCoord];
    const float* latent = (const float*)d_in[iLat];
    const float* W0 = (const float*)d_in[iW0]; const float* b0 = (const float*)d_in[iB0];
    const float* W1 = (const float*)d_in[iW1]; const float* b1 = (const float*)d_in[iB1];
    const float* W2 = (const float*)d_in[iW2]; const float* b2 = (const float*)d_in[iB2];
    const float* W3 = (const float*)d_in[iW3]; const float* b3 = (const float*)d_in[iB3];
    const float* W4 = (const float*)d_in[iW4]; const float* b4 = (const float*)d_in[iB4];

    int blocks = (int)((outN + MTILE - 1) / MTILE);   // 8192 expected
    lisa_kernel<<<blocks, 256>>>(coord, latent,
                                 W0, b0, W1, b1, W2, b2, W3, b3, W4, b4,
                                 (float*)d_out, sz);
}